// round 13
// baseline (speedup 1.0000x reference)
#include <cuda_runtime.h>
#include <cuda_bf16.h>
#include <cstdint>

#define NN 50000
#define EE 800000
#define DD 128
#define NB 49                 // scan blocks: ceil(50000/1024)
#define GB 782                // gemm groups: ceil(50000/64)
#define AGGB 12500            // agg blocks: 50000/4 nodes per block
#define SG 17                 // supergroup: 16 agg blocks + 1 gemm block
#define LAG 48                // gemm lags its producers by LAG supergroups
#define LGRID ((GB + LAG) * SG)

// ---- device scratch (no allocs allowed) ----
__device__ float g_agg[NN * DD];
__device__ float g_h1[NN * DD];
__device__ float g_h2[NN * DD];
__device__ uint32_t g_whi[6 * 8192], g_wlo[6 * 8192];
__device__ int   g_cnt[NN];
__device__ int   g_pos[NN];
__device__ int   g_row[NN + 1];
__device__ float g_inv[NN];
__device__ int   g_srcl[EE];
__device__ int   g_is64;
__device__ int   g_bsum[64];
__device__ int   g_boff[64];
__device__ int   g_done;
__device__ int   g_grp[3 * GB];   // per-layer group completion counters

// ---------------- bf16 split helper ----------------
__device__ __forceinline__ void split2(float x, float y, uint32_t& hi, uint32_t& lo) {
    __nv_bfloat16 hx = __float2bfloat16(x);
    __nv_bfloat16 hy = __float2bfloat16(y);
    __nv_bfloat16 lx = __float2bfloat16(x - __bfloat162float(hx));
    __nv_bfloat16 ly = __float2bfloat16(y - __bfloat162float(hy));
    hi = (uint32_t)__bfloat16_as_ushort(hx) | ((uint32_t)__bfloat16_as_ushort(hy) << 16);
    lo = (uint32_t)__bfloat16_as_ushort(lx) | ((uint32_t)__bfloat16_as_ushort(ly) << 16);
}

// ---------------- edge dtype detection + scratch zeroing ----------------
__global__ void k_detect(const int* __restrict__ eiw) {
    int i = blockIdx.x * blockDim.x + threadIdx.x;
    if (i < NN) g_cnt[i] = 0;
    if (i < 3 * GB) g_grp[i] = 0;
    if (i == 0) g_done = 0;
    if (blockIdx.x == 0 && threadIdx.x < 32) {
        int t = threadIdx.x;
        int bad = 0;
        for (int k = 2 * t + 1; k < 4096; k += 64)
            if (eiw[k] != 0) bad = 1;
        unsigned m = __ballot_sync(0xffffffffu, bad);
        if (t == 0) g_is64 = (m == 0);
    }
}
__device__ __forceinline__ int edge_at(const int* __restrict__ eiw, int idx) {
    return g_is64 ? eiw[2 * idx] : eiw[idx];
}

// ---------------- CSR count + (folded) weight pre-split ----------------
__global__ void k_count(const int* __restrict__ eiw,
                        const float* __restrict__ W0, const float* __restrict__ W1,
                        const float* __restrict__ W2, const float* __restrict__ W3,
                        const float* __restrict__ W4, const float* __restrict__ W5) {
    int e = blockIdx.x * blockDim.x + threadIdx.x;
    if (e < 6 * 8192) {
        const float* Ws[6] = { W0, W1, W2, W3, W4, W5 };
        const float* W = Ws[e >> 13];
        int r = e & 8191;
        float2 v = *(const float2*)(W + r * 2);
        split2(v.x, v.y, g_whi[e], g_wlo[e]);
    }
    if (e < EE) atomicAdd(&g_cnt[edge_at(eiw, EE + e)], 1);
}

// scan over g_cnt; last block also scans the 49 block sums (ticket)
__global__ void __launch_bounds__(1024) k_scan1() {
    int b = blockIdx.x, t = threadIdx.x;
    int i = b * 1024 + t;
    int v = (i < NN) ? g_cnt[i] : 0;
    int lane = t & 31, w = t >> 5;
    int x = v;
#pragma unroll
    for (int o = 1; o < 32; o <<= 1) {
        int y = __shfl_up_sync(0xffffffffu, x, o);
        if (lane >= o) x += y;
    }
    __shared__ int ws[32];
    __shared__ int lastb;
    if (lane == 31) ws[w] = x;
    __syncthreads();
    if (w == 0) {
        int y = ws[lane];
#pragma unroll
        for (int o = 1; o < 32; o <<= 1) {
            int z = __shfl_up_sync(0xffffffffu, y, o);
            if (lane >= o) y += z;
        }
        ws[lane] = y;
    }
    __syncthreads();
    int incl = x + (w > 0 ? ws[w - 1] : 0);
    if (i < NN) g_row[i] = incl - v;
    if (t == 1023) g_bsum[b] = incl;
    if (t == 0) {
        __threadfence();
        int c = atomicAdd(&g_done, 1);
        lastb = (c == NB - 1);
    }
    __syncthreads();
    if (lastb && w == 0) {
        __threadfence();
        int v0 = (lane < NB) ? g_bsum[lane] : 0;
        int v1 = (32 + lane < NB) ? g_bsum[32 + lane] : 0;
        int x0 = v0, x1 = v1;
#pragma unroll
        for (int o = 1; o < 32; o <<= 1) {
            int y = __shfl_up_sync(0xffffffffu, x0, o);
            if (lane >= o) x0 += y;
        }
        int tot0 = __shfl_sync(0xffffffffu, x0, 31);
#pragma unroll
        for (int o = 1; o < 32; o <<= 1) {
            int y = __shfl_up_sync(0xffffffffu, x1, o);
            if (lane >= o) x1 += y;
        }
        if (lane < NB) g_boff[lane] = x0 - v0;
        if (32 + lane < NB) g_boff[32 + lane] = tot0 + x1 - v1;
        if (lane == 31) g_row[NN] = tot0 + __shfl_sync(0xffffffffu, x1, 31);
    }
}
__global__ void __launch_bounds__(1024) k_scan3() {
    int i = blockIdx.x * 1024 + threadIdx.x;
    if (i < NN) {
        int r = g_row[i] + g_boff[blockIdx.x];
        g_row[i] = r;
        g_pos[i] = r;
        int c = g_cnt[i];
        g_inv[i] = 1.0f / (float)(c > 0 ? c : 1);
    }
}
__global__ void k_fill(const int* __restrict__ eiw) {
    int e = blockIdx.x * blockDim.x + threadIdx.x;
    if (e < EE) {
        int d = edge_at(eiw, EE + e);
        int p = atomicAdd(&g_pos[d], 1);
        g_srcl[p] = edge_at(eiw, e);
    }
}

// ================= HMMA core =================
__device__ __forceinline__ void mma_bf16(float* d,
    uint32_t a0, uint32_t a1, uint32_t a2, uint32_t a3,
    uint32_t b0, uint32_t b1)
{
    asm volatile(
        "mma.sync.aligned.m16n8k16.row.col.f32.bf16.bf16.f32 "
        "{%0,%1,%2,%3}, {%4,%5,%6,%7}, {%8,%9}, {%0,%1,%2,%3};"
        : "+f"(d[0]), "+f"(d[1]), "+f"(d[2]), "+f"(d[3])
        : "r"(a0), "r"(a1), "r"(a2), "r"(a3), "r"(b0), "r"(b1));
}

#define RS 20   // smem row stride in u32 (16 data + 4 pad)

// One K=128 GEMM phase: acc += split(A[64 rows from n0]) x split-W^T
__device__ __forceinline__ void hmma_phase(
    const float4* __restrict__ A4,
    const uint32_t* __restrict__ Wh, const uint32_t* __restrict__ Wb,
    int n0, int t,
    uint32_t* sAhi, uint32_t* sAlo, uint32_t* sWhi, uint32_t* sWlo,
    float acc[2][8][4])
{
    int lane = t & 31, w = t >> 5;
    int g = lane >> 2, tig = lane & 3;
    int mi = w & 1, ni = w >> 1;
#pragma unroll 1
    for (int kc = 0; kc < 4; ++kc) {
        // A chunk: 64 rows x 32 k floats, split in-kernel
#pragma unroll
        for (int rep = 0; rep < 4; ++rep) {
            int idx = rep * 128 + t;      // 0..511
            int r = idx >> 3, q = idx & 7;
            int n = n0 + r;
            float4 va = make_float4(0.f, 0.f, 0.f, 0.f);
            if (n < NN) va = A4[(size_t)n * 32 + kc * 8 + q];
            uint32_t h0, l0, h1, l1;
            split2(va.x, va.y, h0, l0);
            split2(va.z, va.w, h1, l1);
            int base = r * RS + q * 2;
            sAhi[base] = h0; sAhi[base + 1] = h1;
            sAlo[base] = l0; sAlo[base + 1] = l1;
        }
        // W chunk: 128 rows x 16 u32, pure uint4 copies from pre-split
#pragma unroll
        for (int rep = 0; rep < 4; ++rep) {
            int idx = rep * 128 + t;      // 0..511
            int r = idx >> 2, q = idx & 3;
            int src = r * 64 + kc * 16 + q * 4;
            int dst = r * RS + q * 4;
            *(uint4*)(sWhi + dst) = *(const uint4*)(Wh + src);
            *(uint4*)(sWlo + dst) = *(const uint4*)(Wb + src);
        }
        __syncthreads();
#pragma unroll
        for (int ks = 0; ks < 2; ++ks) {
            int kof = ks * 8;
            uint32_t ahi[2][4], alo[2][4];
#pragma unroll
            for (int ms = 0; ms < 2; ++ms) {
                int rb = (mi * 32 + ms * 16 + g) * RS + kof + tig;
                int rb8 = rb + 8 * RS;
                ahi[ms][0] = sAhi[rb];     ahi[ms][1] = sAhi[rb8];
                ahi[ms][2] = sAhi[rb + 4]; ahi[ms][3] = sAhi[rb8 + 4];
                alo[ms][0] = sAlo[rb];     alo[ms][1] = sAlo[rb8];
                alo[ms][2] = sAlo[rb + 4]; alo[ms][3] = sAlo[rb8 + 4];
            }
#pragma unroll
            for (int ns = 0; ns < 8; ++ns) {
                int ob = (ni * 64 + ns * 8 + g) * RS + kof + tig;
                uint32_t bh0 = sWhi[ob], bh1 = sWhi[ob + 4];
                uint32_t bl0 = sWlo[ob], bl1 = sWlo[ob + 4];
#pragma unroll
                for (int ms = 0; ms < 2; ++ms) {
                    mma_bf16(acc[ms][ns], ahi[ms][0], ahi[ms][1], ahi[ms][2], ahi[ms][3], bh0, bh1);
                    mma_bf16(acc[ms][ns], alo[ms][0], alo[ms][1], alo[ms][2], alo[ms][3], bh0, bh1);
                    mma_bf16(acc[ms][ns], ahi[ms][0], ahi[ms][1], ahi[ms][2], ahi[ms][3], bl0, bl1);
                }
            }
        }
        __syncthreads();
    }
}

// ================= fused layer: interleaved agg + GEMM =================
// Supergroups of 17 blocks: r<16 -> aggregation block (4 nodes, warp/node,
// MLP-4 batched gather), r==16 -> GEMM block for group (s - LAG): does the
// independent self-phase first, then spins on its group's counter, then
// the agg phase. Layer 3 fuses the decoder.
__global__ void __launch_bounds__(128, 5) k_layer(
    const float* __restrict__ hext, int sel, int widx,
    const float* __restrict__ bias,
    float* out_ext, int osel, int do_relu,
    const float* __restrict__ Wo, const float* __restrict__ bo,
    float* __restrict__ out2)
{
    const float* h = (sel == 1) ? (const float*)g_h1
                   : (sel == 2) ? (const float*)g_h2 : hext;
    float* out = (osel == 1) ? (float*)g_h1
               : (osel == 2) ? (float*)g_h2 : out_ext;

    __shared__ uint32_t sAhi[64 * RS], sAlo[64 * RS];
    __shared__ uint32_t sWhi[128 * RS], sWlo[128 * RS];
    __shared__ float sred[64 * 2 * 2];

    int bid = blockIdx.x;
    int s = bid / SG, r = bid - s * SG;
    int t = threadIdx.x;
    int lane = t & 31, w = t >> 5;

    if (r < 16) {
        // ---- aggregation block: nodes 4*ab .. 4*ab+3, one warp per node ----
        int ab = s * 16 + r;
        if (ab >= AGGB) return;
        int n = ab * 4 + w;                 // always < NN
        int e0 = g_row[n], e1 = g_row[n + 1];
        const float4* h4 = (const float4*)h;
        float4 acc = make_float4(0.f, 0.f, 0.f, 0.f);
        int i = e0;
        for (; i + 3 < e1; i += 4) {        // MLP-4 batched gather
            int s0 = g_srcl[i],     s1 = g_srcl[i + 1];
            int s2 = g_srcl[i + 2], s3 = g_srcl[i + 3];
            float4 v0 = h4[(size_t)s0 * 32 + lane];
            float4 v1 = h4[(size_t)s1 * 32 + lane];
            float4 v2 = h4[(size_t)s2 * 32 + lane];
            float4 v3 = h4[(size_t)s3 * 32 + lane];
            acc.x += (v0.x + v1.x) + (v2.x + v3.x);
            acc.y += (v0.y + v1.y) + (v2.y + v3.y);
            acc.z += (v0.z + v1.z) + (v2.z + v3.z);
            acc.w += (v0.w + v1.w) + (v2.w + v3.w);
        }
        for (; i < e1; ++i) {
            float4 v = h4[(size_t)g_srcl[i] * 32 + lane];
            acc.x += v.x; acc.y += v.y; acc.z += v.z; acc.w += v.w;
        }
        float iv = g_inv[n];
        *(float4*)(g_agg + (size_t)n * DD + lane * 4) =
            make_float4(acc.x * iv, acc.y * iv, acc.z * iv, acc.w * iv);
        __syncthreads();
        __threadfence();
        if (t == 0) atomicAdd(&g_grp[widx * GB + (ab >> 4)], 1);
        return;
    }

    // ---- GEMM block ----
    int grp = s - LAG;
    if (grp < 0 || grp >= GB) return;
    int n0 = grp * 64;
    int g = lane >> 2, tig = lane & 3;
    int mi = w & 1, ni = w >> 1;

    float acc[2][8][4];
#pragma unroll
    for (int ms = 0; ms < 2; ++ms)
#pragma unroll
        for (int ns = 0; ns < 8; ++ns)
#pragma unroll
            for (int q = 0; q < 4; ++q) acc[ms][ns][q] = 0.f;

    // self phase (independent of aggregation): h · Wr^T
    hmma_phase((const float4*)h,
               g_whi + (2 * widx + 1) * 8192, g_wlo + (2 * widx + 1) * 8192,
               n0, t, sAhi, sAlo, sWhi, sWlo, acc);

    // wait for this group's aggregation
    if (t == 0) {
        int expect = AGGB - (grp << 4);
        if (expect > 16) expect = 16;
        volatile int* cp = &g_grp[widx * GB + grp];
        while (*cp < expect) __nanosleep(64);
        __threadfence();
    }
    __syncthreads();

    // agg phase: g_agg · Wl^T
    hmma_phase((const float4*)g_agg,
               g_whi + (2 * widx) * 8192, g_wlo + (2 * widx) * 8192,
               n0, t, sAhi, sAlo, sWhi, sWlo, acc);

    // ---- epilogue: bias + relu + store (+ fused decoder on layer 3) ----
    float p[4][2];
#pragma unroll
    for (int i = 0; i < 4; i++) { p[i][0] = 0.f; p[i][1] = 0.f; }

#pragma unroll
    for (int ms = 0; ms < 2; ++ms) {
        int row0 = n0 + mi * 32 + ms * 16 + g;
        int row1 = row0 + 8;
#pragma unroll
        for (int ns = 0; ns < 8; ++ns) {
            int col = ni * 64 + ns * 8 + 2 * tig;
            float b0 = bias[col], b1 = bias[col + 1];
            float v00 = acc[ms][ns][0] + b0, v01 = acc[ms][ns][1] + b1;
            float v10 = acc[ms][ns][2] + b0, v11 = acc[ms][ns][3] + b1;
            if (do_relu) {
                v00 = fmaxf(v00, 0.f); v01 = fmaxf(v01, 0.f);
                v10 = fmaxf(v10, 0.f); v11 = fmaxf(v11, 0.f);
            }
            if (out2) {
                float wo0a = __ldg(&Wo[col]),      wo0b = __ldg(&Wo[col + 1]);
                float wo1a = __ldg(&Wo[DD + col]), wo1b = __ldg(&Wo[DD + col + 1]);
                p[ms * 2 + 0][0] += v00 * wo0a + v01 * wo0b;
                p[ms * 2 + 0][1] += v00 * wo1a + v01 * wo1b;
                p[ms * 2 + 1][0] += v10 * wo0a + v11 * wo0b;
                p[ms * 2 + 1][1] += v10 * wo1a + v11 * wo1b;
            }
            if (row0 < NN) *(float2*)(out + (size_t)row0 * DD + col) = make_float2(v00, v01);
            if (row1 < NN) *(float2*)(out + (size_t)row1 * DD + col) = make_float2(v10, v11);
        }
    }

    if (out2) {
#pragma unroll
        for (int i = 0; i < 4; i++)
#pragma unroll
            for (int o = 0; o < 2; o++) {
                p[i][o] += __shfl_xor_sync(0xffffffffu, p[i][o], 1);
                p[i][o] += __shfl_xor_sync(0xffffffffu, p[i][o], 2);
            }
        if (tig == 0) {
#pragma unroll
            for (int ms = 0; ms < 2; ++ms)
#pragma unroll
                for (int rr = 0; rr < 2; ++rr) {
                    int lr = mi * 32 + ms * 16 + rr * 8 + g;
#pragma unroll
                    for (int o = 0; o < 2; o++)
                        sred[(lr * 2 + o) * 2 + ni] = p[ms * 2 + rr][o];
                }
        }
        __syncthreads();
        int lr = t >> 1, o = t & 1;
        int n = n0 + lr;
        if (n < NN) {
            float sv = sred[(lr * 2 + o) * 2] + sred[(lr * 2 + o) * 2 + 1] + bo[o];
            out2[n * 2 + o] = sv;
        }
    }
}

extern "C" void kernel_launch(void* const* d_in, const int* in_sizes, int n_in,
                              void* d_out, int out_size) {
    const float* x   = (const float*)d_in[0];
    const int*   eiw = (const int*)d_in[1];
    const float* Wl1 = (const float*)d_in[2];
    const float* Wr1 = (const float*)d_in[3];
    const float* b1  = (const float*)d_in[4];
    const float* Wl2 = (const float*)d_in[5];
    const float* Wr2 = (const float*)d_in[6];
    const float* b2  = (const float*)d_in[7];
    const float* Wl3 = (const float*)d_in[8];
    const float* Wr3 = (const float*)d_in[9];
    const float* b3  = (const float*)d_in[10];
    const float* Wo  = (const float*)d_in[11];
    const float* bo  = (const float*)d_in[12];

    float* out  = (float*)d_out;
    float* out2 = out;              // [N, 2]
    float* h3   = out + NN * 2;     // [N, 128]

    // CSR build + weight pre-split (folded into count)
    k_detect<<<196, 256>>>(eiw);
    k_count<<<(EE + 255) / 256, 256>>>(eiw, Wl1, Wr1, Wl2, Wr2, Wl3, Wr3);
    k_scan1<<<NB, 1024>>>();
    k_scan3<<<NB, 1024>>>();
    k_fill<<<(EE + 255) / 256, 256>>>(eiw);

    // fused layers (agg + GEMM overlapped inside one kernel each)
    k_layer<<<LGRID, 128>>>(x, 0, 0, b1, nullptr, 1, 1, nullptr, nullptr, nullptr);
    k_layer<<<LGRID, 128>>>(nullptr, 1, 1, b2, nullptr, 2, 1, nullptr, nullptr, nullptr);
    k_layer<<<LGRID, 128>>>(nullptr, 2, 2, b3, h3, 0, 0, Wo, bo, out2);
}

// round 14
// speedup vs baseline: 1.8298x; 1.8298x over previous
#include <cuda_runtime.h>
#include <cuda_bf16.h>
#include <cstdint>

#define NN 50000
#define EE 800000
#define DD 128
#define NB 49                 // scan blocks: ceil(50000/1024)
#define GB 782                // gemm blocks: ceil(50000/64)

// ---- device scratch (no allocs allowed) ----
__device__ float g_agg[NN * DD];
__device__ float g_h1[NN * DD];
__device__ float g_h2[NN * DD];
__device__ uint32_t g_whi[6 * 8192], g_wlo[6 * 8192];
__device__ int   g_cnt[NN];
__device__ int   g_pos[NN];
__device__ int   g_row[NN + 1];
__device__ float g_inv[NN];
__device__ int   g_srcl[EE];
__device__ int   g_is64;
__device__ int   g_bsum[64];
__device__ int   g_boff[64];
__device__ int   g_done;

// ---------------- bf16 split helper ----------------
__device__ __forceinline__ void split2(float x, float y, uint32_t& hi, uint32_t& lo) {
    __nv_bfloat16 hx = __float2bfloat16(x);
    __nv_bfloat16 hy = __float2bfloat16(y);
    __nv_bfloat16 lx = __float2bfloat16(x - __bfloat162float(hx));
    __nv_bfloat16 ly = __float2bfloat16(y - __bfloat162float(hy));
    hi = (uint32_t)__bfloat16_as_ushort(hx) | ((uint32_t)__bfloat16_as_ushort(hy) << 16);
    lo = (uint32_t)__bfloat16_as_ushort(lx) | ((uint32_t)__bfloat16_as_ushort(ly) << 16);
}

// ---------------- edge dtype detection + scratch zeroing ----------------
__global__ void k_detect(const int* __restrict__ eiw) {
    int i = blockIdx.x * blockDim.x + threadIdx.x;
    if (i < NN) g_cnt[i] = 0;
    if (i == 0) g_done = 0;
    if (blockIdx.x == 0 && threadIdx.x < 32) {
        int t = threadIdx.x;
        int bad = 0;
        for (int k = 2 * t + 1; k < 4096; k += 64)
            if (eiw[k] != 0) bad = 1;
        unsigned m = __ballot_sync(0xffffffffu, bad);
        if (t == 0) g_is64 = (m == 0);
    }
}
__device__ __forceinline__ int edge_at(const int* __restrict__ eiw, int idx) {
    return g_is64 ? eiw[2 * idx] : eiw[idx];
}

// ---------------- CSR count + (folded) weight pre-split ----------------
__global__ void k_count(const int* __restrict__ eiw,
                        const float* __restrict__ W0, const float* __restrict__ W1,
                        const float* __restrict__ W2, const float* __restrict__ W3,
                        const float* __restrict__ W4, const float* __restrict__ W5) {
    int e = blockIdx.x * blockDim.x + threadIdx.x;
    if (e < 6 * 8192) {
        const float* Ws[6] = { W0, W1, W2, W3, W4, W5 };
        const float* W = Ws[e >> 13];
        int r = e & 8191;
        float2 v = *(const float2*)(W + r * 2);
        split2(v.x, v.y, g_whi[e], g_wlo[e]);
    }
    if (e < EE) atomicAdd(&g_cnt[edge_at(eiw, EE + e)], 1);
}

// scan over g_cnt; last block also scans the 49 block sums (ticket)
__global__ void __launch_bounds__(1024) k_scan1() {
    int b = blockIdx.x, t = threadIdx.x;
    int i = b * 1024 + t;
    int v = (i < NN) ? g_cnt[i] : 0;
    int lane = t & 31, w = t >> 5;
    int x = v;
#pragma unroll
    for (int o = 1; o < 32; o <<= 1) {
        int y = __shfl_up_sync(0xffffffffu, x, o);
        if (lane >= o) x += y;
    }
    __shared__ int ws[32];
    __shared__ int lastb;
    if (lane == 31) ws[w] = x;
    __syncthreads();
    if (w == 0) {
        int y = ws[lane];
#pragma unroll
        for (int o = 1; o < 32; o <<= 1) {
            int z = __shfl_up_sync(0xffffffffu, y, o);
            if (lane >= o) y += z;
        }
        ws[lane] = y;
    }
    __syncthreads();
    int incl = x + (w > 0 ? ws[w - 1] : 0);
    if (i < NN) g_row[i] = incl - v;
    if (t == 1023) g_bsum[b] = incl;
    if (t == 0) {
        __threadfence();
        int c = atomicAdd(&g_done, 1);
        lastb = (c == NB - 1);
    }
    __syncthreads();
    if (lastb && w == 0) {
        __threadfence();
        int v0 = (lane < NB) ? g_bsum[lane] : 0;
        int v1 = (32 + lane < NB) ? g_bsum[32 + lane] : 0;
        int x0 = v0, x1 = v1;
#pragma unroll
        for (int o = 1; o < 32; o <<= 1) {
            int y = __shfl_up_sync(0xffffffffu, x0, o);
            if (lane >= o) x0 += y;
        }
        int tot0 = __shfl_sync(0xffffffffu, x0, 31);
#pragma unroll
        for (int o = 1; o < 32; o <<= 1) {
            int y = __shfl_up_sync(0xffffffffu, x1, o);
            if (lane >= o) x1 += y;
        }
        if (lane < NB) g_boff[lane] = x0 - v0;
        if (32 + lane < NB) g_boff[32 + lane] = tot0 + x1 - v1;
        if (lane == 31) g_row[NN] = tot0 + __shfl_sync(0xffffffffu, x1, 31);
    }
}
__global__ void __launch_bounds__(1024) k_scan3() {
    int i = blockIdx.x * 1024 + threadIdx.x;
    if (i < NN) {
        int r = g_row[i] + g_boff[blockIdx.x];
        g_row[i] = r;
        g_pos[i] = r;
        int c = g_cnt[i];
        g_inv[i] = 1.0f / (float)(c > 0 ? c : 1);
    }
}
__global__ void k_fill(const int* __restrict__ eiw) {
    int e = blockIdx.x * blockDim.x + threadIdx.x;
    if (e < EE) {
        int d = edge_at(eiw, EE + e);
        int p = atomicAdd(&g_pos[d], 1);
        g_srcl[p] = edge_at(eiw, e);
    }
}

// ---------------- mean aggregation: one warp per node ----------------
__global__ void k_aggregate(const float* __restrict__ hext, int sel) {
    const float* h = (sel == 1) ? (const float*)g_h1
                   : (sel == 2) ? (const float*)g_h2 : hext;
    int w = (blockIdx.x * blockDim.x + threadIdx.x) >> 5;
    int lane = threadIdx.x & 31;
    if (w >= NN) return;
    int s = g_row[w], e = g_row[w + 1];
    float4 acc = make_float4(0.f, 0.f, 0.f, 0.f);
    for (int i = s; i < e; ++i) {
        int src = g_srcl[i];
        float4 v = *(const float4*)(h + (size_t)src * DD + lane * 4);
        acc.x += v.x; acc.y += v.y; acc.z += v.z; acc.w += v.w;
    }
    float iv = g_inv[w];
    *(float4*)(g_agg + (size_t)w * DD + lane * 4) =
        make_float4(acc.x * iv, acc.y * iv, acc.z * iv, acc.w * iv);
}

// ================= HMMA bf16 3-product fused SAGE GEMM =================
// out = relu?( agg·Wl^T + h·Wr^T + b ); fp32 emulated via bf16 split
// (Ahi·Bhi + Alo·Bhi + Ahi·Blo). 64-row x 128-col CTA tile, 128 threads
// (2 m-warps x 2 n-warps). A split in-kernel from fp32; W pre-split in
// global, filled with pure uint4 copies. Layer 3 fuses the decoder.
__device__ __forceinline__ void mma_bf16(float* d,
    uint32_t a0, uint32_t a1, uint32_t a2, uint32_t a3,
    uint32_t b0, uint32_t b1)
{
    asm volatile(
        "mma.sync.aligned.m16n8k16.row.col.f32.bf16.bf16.f32 "
        "{%0,%1,%2,%3}, {%4,%5,%6,%7}, {%8,%9}, {%0,%1,%2,%3};"
        : "+f"(d[0]), "+f"(d[1]), "+f"(d[2]), "+f"(d[3])
        : "r"(a0), "r"(a1), "r"(a2), "r"(a3), "r"(b0), "r"(b1));
}

#define RS 20   // smem row stride in u32 (16 data + 4 pad)

__global__ void __launch_bounds__(128, 5) k_gemm(
    const float* __restrict__ aself_ext, int asel,
    int widx,          // weight pair index: Wl at 2*widx, Wr at 2*widx+1
    const float* __restrict__ bias,
    float* out_ext, int osel, int do_relu,
    const float* __restrict__ Wo, const float* __restrict__ bo,
    float* __restrict__ out2)
{
    const float* Aself = (asel == 1) ? (const float*)g_h1
                       : (asel == 2) ? (const float*)g_h2 : aself_ext;
    float* out = (osel == 1) ? (float*)g_h1
               : (osel == 2) ? (float*)g_h2 : out_ext;

    __shared__ uint32_t sAhi[64 * RS], sAlo[64 * RS];
    __shared__ uint32_t sWhi[128 * RS], sWlo[128 * RS];
    __shared__ float sred[64 * 2 * 2];     // decoder reduce: [row][out][ni]

    int t = threadIdx.x;
    int lane = t & 31, w = t >> 5;
    int g = lane >> 2, tig = lane & 3;
    int mi = w & 1, ni = w >> 1;          // 2 m-warps x 2 n-warps
    int n0 = blockIdx.x * 64;

    float acc[2][8][4];
#pragma unroll
    for (int ms = 0; ms < 2; ++ms)
#pragma unroll
        for (int ns = 0; ns < 8; ++ns)
#pragma unroll
            for (int q = 0; q < 4; ++q) acc[ms][ns][q] = 0.f;

#pragma unroll 1
    for (int phase = 0; phase < 2; ++phase) {
        const float4* A4 = (const float4*)(phase ? Aself : (const float*)g_agg);
        const uint32_t* Wh = g_whi + (2 * widx + phase) * 8192;
        const uint32_t* Wb = g_wlo + (2 * widx + phase) * 8192;
#pragma unroll 1
        for (int kc = 0; kc < 4; ++kc) {
            // A chunk: 64 rows x 32 k floats, split in-kernel
#pragma unroll
            for (int rep = 0; rep < 4; ++rep) {
                int idx = rep * 128 + t;      // 0..511
                int r = idx >> 3, q = idx & 7;
                int n = n0 + r;
                float4 va = make_float4(0.f, 0.f, 0.f, 0.f);
                if (n < NN) va = A4[(size_t)n * 32 + kc * 8 + q];
                uint32_t h0, l0, h1, l1;
                split2(va.x, va.y, h0, l0);
                split2(va.z, va.w, h1, l1);
                int base = r * RS + q * 2;
                sAhi[base] = h0; sAhi[base + 1] = h1;
                sAlo[base] = l0; sAlo[base + 1] = l1;
            }
            // W chunk: 128 rows x 16 u32, pure uint4 copies from pre-split
#pragma unroll
            for (int rep = 0; rep < 4; ++rep) {
                int idx = rep * 128 + t;      // 0..511
                int r = idx >> 2, q = idx & 3;
                int src = r * 64 + kc * 16 + q * 4;
                int dst = r * RS + q * 4;
                *(uint4*)(sWhi + dst) = *(const uint4*)(Wh + src);
                *(uint4*)(sWlo + dst) = *(const uint4*)(Wb + src);
            }
            __syncthreads();
#pragma unroll
            for (int ks = 0; ks < 2; ++ks) {
                int kof = ks * 8;
                uint32_t ahi[2][4], alo[2][4];
#pragma unroll
                for (int ms = 0; ms < 2; ++ms) {
                    int rb = (mi * 32 + ms * 16 + g) * RS + kof + tig;
                    int rb8 = rb + 8 * RS;
                    ahi[ms][0] = sAhi[rb];     ahi[ms][1] = sAhi[rb8];
                    ahi[ms][2] = sAhi[rb + 4]; ahi[ms][3] = sAhi[rb8 + 4];
                    alo[ms][0] = sAlo[rb];     alo[ms][1] = sAlo[rb8];
                    alo[ms][2] = sAlo[rb + 4]; alo[ms][3] = sAlo[rb8 + 4];
                }
#pragma unroll
                for (int ns = 0; ns < 8; ++ns) {
                    int ob = (ni * 64 + ns * 8 + g) * RS + kof + tig;
                    uint32_t bh0 = sWhi[ob], bh1 = sWhi[ob + 4];
                    uint32_t bl0 = sWlo[ob], bl1 = sWlo[ob + 4];
#pragma unroll
                    for (int ms = 0; ms < 2; ++ms) {
                        mma_bf16(acc[ms][ns], ahi[ms][0], ahi[ms][1], ahi[ms][2], ahi[ms][3], bh0, bh1);
                        mma_bf16(acc[ms][ns], alo[ms][0], alo[ms][1], alo[ms][2], alo[ms][3], bh0, bh1);
                        mma_bf16(acc[ms][ns], ahi[ms][0], ahi[ms][1], ahi[ms][2], ahi[ms][3], bl0, bl1);
                    }
                }
            }
            __syncthreads();
        }
    }

    // epilogue: bias + relu + store (+ fused decoder partials on layer 3)
    float p[4][2];
#pragma unroll
    for (int i = 0; i < 4; i++) { p[i][0] = 0.f; p[i][1] = 0.f; }

#pragma unroll
    for (int ms = 0; ms < 2; ++ms) {
        int row0 = n0 + mi * 32 + ms * 16 + g;
        int row1 = row0 + 8;
#pragma unroll
        for (int ns = 0; ns < 8; ++ns) {
            int col = ni * 64 + ns * 8 + 2 * tig;
            float b0 = bias[col], b1 = bias[col + 1];
            float v00 = acc[ms][ns][0] + b0, v01 = acc[ms][ns][1] + b1;
            float v10 = acc[ms][ns][2] + b0, v11 = acc[ms][ns][3] + b1;
            if (do_relu) {
                v00 = fmaxf(v00, 0.f); v01 = fmaxf(v01, 0.f);
                v10 = fmaxf(v10, 0.f); v11 = fmaxf(v11, 0.f);
            }
            if (out2) {
                float wo0a = __ldg(&Wo[col]),      wo0b = __ldg(&Wo[col + 1]);
                float wo1a = __ldg(&Wo[DD + col]), wo1b = __ldg(&Wo[DD + col + 1]);
                p[ms * 2 + 0][0] += v00 * wo0a + v01 * wo0b;
                p[ms * 2 + 0][1] += v00 * wo1a + v01 * wo1b;
                p[ms * 2 + 1][0] += v10 * wo0a + v11 * wo0b;
                p[ms * 2 + 1][1] += v10 * wo1a + v11 * wo1b;
            }
            if (row0 < NN) *(float2*)(out + (size_t)row0 * DD + col) = make_float2(v00, v01);
            if (row1 < NN) *(float2*)(out + (size_t)row1 * DD + col) = make_float2(v10, v11);
        }
    }

    if (out2) {
#pragma unroll
        for (int i = 0; i < 4; i++)
#pragma unroll
            for (int o = 0; o < 2; o++) {
                p[i][o] += __shfl_xor_sync(0xffffffffu, p[i][o], 1);
                p[i][o] += __shfl_xor_sync(0xffffffffu, p[i][o], 2);
            }
        if (tig == 0) {
#pragma unroll
            for (int ms = 0; ms < 2; ++ms)
#pragma unroll
                for (int rr = 0; rr < 2; ++rr) {
                    int lr = mi * 32 + ms * 16 + rr * 8 + g;
#pragma unroll
                    for (int o = 0; o < 2; o++)
                        sred[(lr * 2 + o) * 2 + ni] = p[ms * 2 + rr][o];
                }
        }
        __syncthreads();
        int lr = t >> 1, o = t & 1;
        int n = n0 + lr;
        if (n < NN) {
            float s = sred[(lr * 2 + o) * 2] + sred[(lr * 2 + o) * 2 + 1] + bo[o];
            out2[n * 2 + o] = s;
        }
    }
}

extern "C" void kernel_launch(void* const* d_in, const int* in_sizes, int n_in,
                              void* d_out, int out_size) {
    const float* x   = (const float*)d_in[0];
    const int*   eiw = (const int*)d_in[1];
    const float* Wl1 = (const float*)d_in[2];
    const float* Wr1 = (const float*)d_in[3];
    const float* b1  = (const float*)d_in[4];
    const float* Wl2 = (const float*)d_in[5];
    const float* Wr2 = (const float*)d_in[6];
    const float* b2  = (const float*)d_in[7];
    const float* Wl3 = (const float*)d_in[8];
    const float* Wr3 = (const float*)d_in[9];
    const float* b3  = (const float*)d_in[10];
    const float* Wo  = (const float*)d_in[11];
    const float* bo  = (const float*)d_in[12];

    float* out  = (float*)d_out;
    float* out2 = out;              // [N, 2]
    float* h3   = out + NN * 2;     // [N, 128]

    // CSR build + weight pre-split (folded into count)
    k_detect<<<196, 256>>>(eiw);
    k_count<<<(EE + 255) / 256, 256>>>(eiw, Wl1, Wr1, Wl2, Wr2, Wl3, Wr3);
    k_scan1<<<NB, 1024>>>();
    k_scan3<<<NB, 1024>>>();
    k_fill<<<(EE + 255) / 256, 256>>>(eiw);

    int warp_blocks = (NN + 7) / 8;

    // layer 1: x -> h1 (relu)
    k_aggregate<<<warp_blocks, 256>>>(x, 0);
    k_gemm<<<GB, 128>>>(x, 0, 0, b1, nullptr, 1, 1, nullptr, nullptr, nullptr);

    // layer 2: h1 -> h2 (relu)
    k_aggregate<<<warp_blocks, 256>>>(nullptr, 1);
    k_gemm<<<GB, 128>>>(nullptr, 1, 1, b2, nullptr, 2, 1, nullptr, nullptr, nullptr);

    // layer 3: h2 -> h3 (no relu) + fused decoder into out2
    k_aggregate<<<warp_blocks, 256>>>(nullptr, 2);
    k_gemm<<<GB, 128>>>(nullptr, 2, 2, b3, h3, 0, 0, Wo, bo, out2);
}